// round 15
// baseline (speedup 1.0000x reference)
#include <cuda_runtime.h>
#include <cuda_fp16.h>
#include <math.h>
#include <stdint.h>

#define B 8
#define L1 384
#define L2 384
#define H 128
#define H2 256
#define H4 512
#define NFLAGS 192   // 24 t-chunks x 8 batches

// ---- scratch (allocation-free: __device__ globals) ----
__device__ float d_xp[B * L1 * H];
__device__ float d_yp[B * L2 * H];
__device__ float d_gx[B * L1 * H4];
__device__ int   d_flags[NFLAGS];

__device__ __forceinline__ float tanh_fast(float x) {
    float y;
    asm("tanh.approx.f32 %0, %1;" : "=f"(y) : "f"(x));
    return y;
}
__device__ __forceinline__ float sigmoid_acc(float x) {
    x = fminf(fmaxf(x, -30.f), 30.f);
    return 1.f / (1.f + __expf(-x));
}
__device__ __forceinline__ float tanh_acc(float x) {
    x = fminf(fmaxf(x, -15.f), 15.f);
    float e = __expf(-2.f * x);
    return (1.f - e) / (1.f + e);
}

// ============================================================
// Kernel A: row projections (+ flag reset, stream-ordered before fused)
// ============================================================
__global__ void k_proj(const float* __restrict__ x, const float* __restrict__ y,
                       const float* __restrict__ Wup, const float* __restrict__ bup,
                       const float* __restrict__ Wq,  const float* __restrict__ bq,
                       const float* __restrict__ bvp)
{
    int row = blockIdx.x;
    int o   = threadIdx.x;

    if (row == 0 && o < 128)            d_flags[o] = 0;
    if (row == 1 && o < NFLAGS - 128)   d_flags[128 + o] = 0;

    __shared__ float4 in4[H / 4];
    const float* in; const float* W; float bias; float* out;
    if (row < B * L1) {
        in = x + (size_t)row * H;  W = Wup;  bias = bup[o];           out = d_xp + (size_t)row * H;
    } else {
        int r = row - B * L1;
        in = y + (size_t)r * H;    W = Wq;   bias = bq[o] + bvp[o];   out = d_yp + (size_t)r * H;
    }
    if (o < H / 4) in4[o] = ((const float4*)in)[o];
    __syncthreads();

    const float4* W4 = (const float4*)(W + (size_t)o * H);
    float acc = bias;
#pragma unroll
    for (int k = 0; k < H / 4; k++) {
        float4 w = W4[k];
        float4 v = in4[k];
        acc += w.x * v.x + w.y * v.y + w.z * v.z + w.w * v.w;
    }
    out[o] = acc;
}

// ============================================================
// Kernel FUSED: full pipeline after projections.
// blocks 0..7   : LSTM (one batch each), consumes d_gx chunk-by-chunk.
// blocks 8..103 : workers; per 16-row (b,t)-chunk (t-ordered):
//                 scores -> softmax (in-smem) -> ctx -> gate -> gx -> flag.
// All 104 blocks resident (<=148 SMs); workers never wait -> no deadlock.
// SMEM (48KB exact): R1 scores 24KB (later ms 16KB),
//                    R2 yp-tile 16KB XOR-swizzled (later ysm 8KB / lis 16KB),
//                    R3 xp tile 8KB.
// ============================================================
__global__ void __launch_bounds__(512, 1)
k_fused(const float* __restrict__ x, const float* __restrict__ y,
        const unsigned char* __restrict__ xmask,
        const unsigned char* __restrict__ ymask,
        const float* __restrict__ Vw, const float* __restrict__ Vb,
        const float* __restrict__ Wg,  const float* __restrict__ bg,
        const float* __restrict__ Wih, const float* __restrict__ bih,
        const float* __restrict__ bhh,
        const float* __restrict__ Whh, float* __restrict__ out)
{
    __shared__ __align__(16) unsigned char sbuf[49152];
    int tid = threadIdx.x;

    if (blockIdx.x < 8) {
        // =============== LSTM consumer (R7 core + chunk polling) ===============
        __half* hs = (__half*)sbuf;
        float*  gs = (float*)(sbuf + 256);
        int b = blockIdx.x;
        int t = tid;

        uint2 wreg[32];
        {
            const float4* wr = (const float4*)(Whh + (size_t)t * H);
#pragma unroll
            for (int kk = 0; kk < 32; kk++) {
                float4 w = wr[kk];
                half2 lo = __floats2half2_rn(w.x, w.y);
                half2 hi = __floats2half2_rn(w.z, w.w);
                wreg[kk].x = *(uint32_t*)&lo;
                wreg[kk].y = *(uint32_t*)&hi;
            }
        }

        if (t < H) hs[t] = __float2half_rn(0.f);
        float c = 0.f;
        const float* __restrict__ gxp = d_gx + (size_t)b * L1 * H4 + t;
        bool is_tanh_gate = ((t >> 7) == 2);
        __syncthreads();
        const uint2* h2p = (const uint2*)hs;

        float gx = 0.f;
        for (int step = 0; step < L1; step++) {
            if ((step & 15) == 0) {
                if (t == 0) {
                    const int* fp = &d_flags[(step >> 4) * 8 + b];
                    int v;
                    do {
                        asm volatile("ld.acquire.gpu.global.b32 %0, [%1];"
                                     : "=r"(v) : "l"(fp) : "memory");
                    } while (v == 0);
                }
                __syncthreads();
                gx = gxp[(size_t)step * H4];
            }
            float gpre = gx;
            if ((step & 15) != 15)
                gx = gxp[(size_t)(step + 1) * H4];

            float facc = 0.f;
#pragma unroll
            for (int ch = 0; ch < 4; ch++) {
                __half2 accA = __float2half2_rn(0.f);
                __half2 accB = __float2half2_rn(0.f);
#pragma unroll
                for (int q = 0; q < 8; q++) {
                    int kk = ch * 8 + q;
                    uint2 hv = h2p[kk];
                    accA = __hfma2(*(const __half2*)&wreg[kk].x,
                                   *(const __half2*)&hv.x, accA);
                    accB = __hfma2(*(const __half2*)&wreg[kk].y,
                                   *(const __half2*)&hv.y, accB);
                }
                float2 fa = __half22float2(accA);
                float2 fb = __half22float2(accB);
                facc += (fa.x + fa.y) + (fb.x + fb.y);
            }
            gpre += facc;

            gs[t] = is_tanh_gate ? tanh_acc(gpre) : sigmoid_acc(gpre);
            __syncthreads();

            if (t < H) {
                float gi = gs[t], gf = gs[t + H], gg = gs[t + 2 * H], go = gs[t + 3 * H];
                c = gf * c + gi * gg;
                float hn = go * tanh_acc(c);
                hs[t] = __float2half_rn(hn);
                out[(size_t)((b * L1) + step) * H + t] = hn;
            }
            __syncthreads();
        }
        return;
    }

    // =============== worker producer ===============
    float*  scores = (float*)sbuf;                     // 16 x 384 (24KB); later ms 16x256
    float4* ypt4   = (float4*)(sbuf + 24576);          // 32 x 32 float4, swizzled (16KB)
    float*  ysm    = (float*)(sbuf + 24576);           // ctx y-tile 16x128 (8KB)
    float*  lis    = (float*)(sbuf + 24576);           // gate tile 16x256 (16KB)
    float4* xs4    = (float4*)(sbuf + 40960);          // xp tile 16 x 32 float4 (8KB)
    float*  ms     = (float*)sbuf;                     // merge tile 16x256 (aliases scores)

    const float4* Vw4 = (const float4*)Vw;
    float vb = Vb[0];
    const float NEG_INF = __int_as_float(0xff800000);

    int w = blockIdx.x - 8;                            // 0..95
    for (int half = 0; half < 2; half++) {
        int cidx = w + half * 96;
        int tc = cidx >> 3;
        int b  = cidx & 7;
        int t0 = tc * 16;

        // ---- stage xp tile (16 rows) ----
        const float4* xp4 = (const float4*)(d_xp + (size_t)(b * L1 + t0) * H);
        if (tid < 16 * 32) xs4[tid] = xp4[tid];
        __syncthreads();

        // ---- scores: s[t][j] = V . tanh(xp[t]+yp[j]) + Vb, masked ----
        int st   = tid >> 5;                           // t row 0..15 (warp-per-row)
        int lane = tid & 31;
        bool xmb = xmask[b * L1 + t0 + st] != 0;
        float xmv = xmb ? 0.f : 1.f;
        const float4* yp4 = (const float4*)(d_yp + (size_t)b * L2 * H);

        for (int jt = 0; jt < 12; jt++) {
            __syncthreads();   // previous tile fully consumed
            // stage yp rows jt*32..+32, XOR-swizzled (slot = r*32 + (k4^r))
            for (int i = tid; i < 32 * 32; i += 512) {
                int r = i >> 5, k4 = i & 31;
                ypt4[r * 32 + (k4 ^ r)] = yp4[(size_t)(jt * 32 + r) * 32 + k4];
            }
            __syncthreads();

            float acc = 0.f;
#pragma unroll 8
            for (int k4 = 0; k4 < 32; k4++) {
                float4 xv = xs4[st * 32 + k4];                   // warp-broadcast
                float4 yv = ypt4[lane * 32 + (k4 ^ lane)];       // conflict-free
                float4 v  = __ldg(&Vw4[k4]);                     // L1-resident
                acc += v.x * tanh_fast(xv.x + yv.x);
                acc += v.y * tanh_fast(xv.y + yv.y);
                acc += v.z * tanh_fast(xv.z + yv.z);
                acc += v.w * tanh_fast(xv.w + yv.w);
            }
            int j = jt * 32 + lane;
            bool ymb = ymask[b * L2 + j] != 0;
            float s = (acc + vb) * (xmv * (ymb ? 0.f : 1.f));
            if (ymb) s = NEG_INF;
            scores[st * 384 + j] = s;
        }
        __syncthreads();

        // ---- softmax in place: warp st handles row st ----
        {
            float* srow = scores + st * 384;
            float v12[12];
            float m = -INFINITY;
#pragma unroll
            for (int i = 0; i < 12; i++) { v12[i] = srow[lane + 32 * i]; m = fmaxf(m, v12[i]); }
#pragma unroll
            for (int o = 16; o > 0; o >>= 1) m = fmaxf(m, __shfl_xor_sync(~0u, m, o));
            float sum = 0.f;
#pragma unroll
            for (int i = 0; i < 12; i++) { v12[i] = __expf(v12[i] - m); sum += v12[i]; }
#pragma unroll
            for (int o = 16; o > 0; o >>= 1) sum += __shfl_xor_sync(~0u, sum, o);
            float inv = 1.0f / sum;
#pragma unroll
            for (int i = 0; i < 12; i++) srow[lane + 32 * i] = v12[i] * inv;
        }
        __syncthreads();

        // ---- ctx: acc[4] over 24 tiles of 16 j (alpha read from scores) ----
        int h  = tid & 127;
        int tg = tid >> 7;                              // 0..3 -> 4 rows each
        float acc[4] = {0.f, 0.f, 0.f, 0.f};

        const float4* y4 = (const float4*)(y + (size_t)b * L2 * H);
        float4 ybuf = y4[tid];

        for (int cj = 0; cj < 24; cj++) {
            __syncthreads();
            ((float4*)ysm)[tid] = ybuf;
            __syncthreads();
            if (cj + 1 < 24) ybuf = y4[(cj + 1) * 512 + tid];

#pragma unroll 8
            for (int jj = 0; jj < 16; jj++) {
                float yv = ysm[jj * 128 + h];
#pragma unroll
                for (int i = 0; i < 4; i++)
                    acc[i] += scores[(tg * 4 + i) * 384 + cj * 16 + jj] * yv;  // broadcast
            }
        }
        __syncthreads();   // all alpha reads done; scores region now reusable as ms

        // ---- merge tile: x cols [0,128), ct cols [128,256) ----
#pragma unroll
        for (int i = 0; i < 4; i++)
            ms[(tg * 4 + i) * 256 + 128 + h] = acc[i];
        for (int i = tid; i < 16 * 128; i += 512) {
            int r = i >> 7, k = i & 127;
            ms[r * 256 + k] = x[(size_t)(b * L1 + t0 + r) * H + k];
        }
        __syncthreads();

        // ---- gate: lis = sigmoid(ms @ Wg^T + bg) * ms ----
        {
            int rg = tid >> 8;
            int cc = tid & 255;
            float a8[8];
#pragma unroll
            for (int r = 0; r < 8; r++) a8[r] = 0.f;

            const float4* W4  = (const float4*)(Wg + (size_t)cc * H2);
            const float4* ms4 = (const float4*)ms;
            for (int k = 0; k < H2 / 4; k++) {
                float4 wv = W4[k];
#pragma unroll
                for (int r = 0; r < 8; r++) {
                    float4 m = ms4[(rg * 8 + r) * (H2 / 4) + k];
                    a8[r] += wv.x * m.x + wv.y * m.y + wv.z * m.z + wv.w * m.w;
                }
            }
            float bias = bg[cc];
#pragma unroll
            for (int r = 0; r < 8; r++) {
                float g = 1.0f / (1.0f + __expf(-(a8[r] + bias)));
                lis[(rg * 8 + r) * 256 + cc] = g * ms[(rg * 8 + r) * 256 + cc];
            }
        }
        __syncthreads();

        // ---- gx = lis @ W_ih^T + (b_ih + b_hh), one col per thread ----
        {
            int col = tid;
            float a16[16];
#pragma unroll
            for (int r = 0; r < 16; r++) a16[r] = 0.f;

            const float4* Wv  = (const float4*)(Wih + (size_t)col * H2);
            const float4* li4 = (const float4*)lis;
            for (int k = 0; k < H2 / 4; k++) {
                float4 wv = Wv[k];
#pragma unroll
                for (int r = 0; r < 16; r++) {
                    float4 m = li4[r * (H2 / 4) + k];
                    a16[r] += wv.x * m.x + wv.y * m.y + wv.z * m.z + wv.w * m.w;
                }
            }
            float bias = bih[col] + bhh[col];
#pragma unroll
            for (int r = 0; r < 16; r++)
                d_gx[(size_t)(b * L1 + t0 + r) * H4 + col] = a16[r] + bias;
        }
        __syncthreads();

        if (tid == 0) {
            asm volatile("st.release.gpu.global.b32 [%0], %1;"
                         :: "l"(&d_flags[cidx]), "r"(1) : "memory");
        }
        __syncthreads();
    }
}

// ============================================================
extern "C" void kernel_launch(void* const* d_in, const int* in_sizes, int n_in,
                              void* d_out, int out_size)
{
    const float*         x     = (const float*)d_in[0];
    const unsigned char* xmask = (const unsigned char*)d_in[1];
    const float*         y     = (const float*)d_in[2];
    const unsigned char* ymask = (const unsigned char*)d_in[3];
    const float* Wq_w  = (const float*)d_in[4];
    const float* Wq_b  = (const float*)d_in[5];
    const float* Wup_w = (const float*)d_in[6];
    const float* Wup_b = (const float*)d_in[7];
    // d_in[8] = Wvp_w (multiplied by zeros in reference -> unused)
    const float* Wvp_b = (const float*)d_in[9];
    const float* V_w   = (const float*)d_in[10];
    const float* V_b   = (const float*)d_in[11];
    const float* Wg_w  = (const float*)d_in[12];
    const float* Wg_b  = (const float*)d_in[13];
    const float* W_ih  = (const float*)d_in[14];
    const float* W_hh  = (const float*)d_in[15];
    const float* b_ih  = (const float*)d_in[16];
    const float* b_hh  = (const float*)d_in[17];
    float* out = (float*)d_out;

    k_proj <<<B * L1 + B * L2, 128>>>(x, y, Wup_w, Wup_b, Wq_w, Wq_b, Wvp_b);
    k_fused<<<104, 512>>>(x, y, xmask, ymask, V_w, V_b,
                          Wg_w, Wg_b, W_ih, b_ih, b_hh, W_hh, out);
}